// round 13
// baseline (speedup 1.0000x reference)
#include <cuda_runtime.h>
#include <math.h>

// ---------------- problem constants ----------------
#define Bv   2
#define Cch  256
#define Nn   32768           // D*H*W
#define Ss   256
#define TDd  512
#define NH   8
#define HD   32
#define SCALE 0.17677669529663687f    // 32^-0.5
#define QSCALE 0.2550396392825023f    // SCALE * log2(e)

// ---------------- scratch ----------------
__device__ float g_krot[Bv * NH * Ss * HD];          // [b,h,s,hd]
__device__ float g_v   [Bv * NH * Ss * HD];          // [b,h,s,hd]
__device__ float g_qrot[(size_t)Bv * NH * Nn * HD];  // [b,h,n,hd]  64MB
__device__ float g_att [(size_t)Bv * Nn * Cch];      // [b,n,c]     64MB

// ---------------- helpers ----------------
__device__ __forceinline__ unsigned f2tf(float x) {
    unsigned u;
    asm("cvt.rna.tf32.f32 %0, %1;" : "=r"(u) : "f"(x));
    return u;
}
__device__ __forceinline__ float tfval(float x) { return __uint_as_float(f2tf(x)); }

__device__ __forceinline__ void mma8(float c[4], const unsigned a[4],
                                     unsigned b0, unsigned b1) {
    asm volatile(
        "mma.sync.aligned.m16n8k8.row.col.f32.tf32.tf32.f32 "
        "{%0,%1,%2,%3},{%4,%5,%6,%7},{%8,%9},{%0,%1,%2,%3};"
        : "+f"(c[0]), "+f"(c[1]), "+f"(c[2]), "+f"(c[3])
        : "r"(a[0]), "r"(a[1]), "r"(a[2]), "r"(a[3]), "r"(b0), "r"(b1));
}

__device__ __forceinline__ void cpasync16(unsigned dst, const void* src) {
    asm volatile("cp.async.ca.shared.global [%0], [%1], 16;" :: "r"(dst), "l"(src));
}
#define CP_COMMIT()  asm volatile("cp.async.commit_group;")
#define CP_WAIT(n)   asm volatile("cp.async.wait_group %0;" :: "n"(n))

// ---------------------------------------------------------------------------
// Kernel 1: text side (K/V proj, MLP phase, rope on K). 64 CTAs, tiny. FFMA.
// ---------------------------------------------------------------------------
__global__ void text_kernel(const float* __restrict__ text,
                            const float* __restrict__ k_w, const float* __restrict__ k_b,
                            const float* __restrict__ v_w, const float* __restrict__ v_b,
                            const float* __restrict__ m1_w, const float* __restrict__ m1_b,
                            const float* __restrict__ m2_w, const float* __restrict__ m2_b)
{
    __shared__ float t_s[8][TDd];
    __shared__ float h_s[8][Cch];
    __shared__ float k_s[8][Cch];

    const int tid  = threadIdx.x;
    const int row0 = blockIdx.x * 8;

    #pragma unroll
    for (int r = 0; r < 8; r++) {
        t_s[r][tid]       = text[(size_t)(row0 + r) * TDd + tid];
        t_s[r][tid + 256] = text[(size_t)(row0 + r) * TDd + tid + 256];
    }
    __syncthreads();

    float ka[8], va[8], ha[8];
    #pragma unroll
    for (int r = 0; r < 8; r++) { ka[r] = k_b[tid]; va[r] = v_b[tid]; ha[r] = m1_b[tid]; }

    for (int i = 0; i < TDd; i++) {
        const float wk = k_w[i * Cch + tid];
        const float wv = v_w[i * Cch + tid];
        const float wm = m1_w[i * Cch + tid];
        #pragma unroll
        for (int r = 0; r < 8; r++) {
            const float t = t_s[r][i];
            ka[r] += t * wk;  va[r] += t * wv;  ha[r] += t * wm;
        }
    }

    #pragma unroll
    for (int r = 0; r < 8; r++) {
        const float x = ha[r];
        h_s[r][tid] = 0.5f * x * (1.0f + erff(x * 0.7071067811865475f));
        k_s[r][tid] = ka[r];
    }
    __syncthreads();

    float pa[8];
    #pragma unroll
    for (int r = 0; r < 8; r++) pa[r] = m2_b[tid];
    for (int i = 0; i < Cch; i++) {
        const float wm2 = m2_w[i * Cch + tid];
        #pragma unroll
        for (int r = 0; r < 8; r++) pa[r] += h_s[r][i] * wm2;
    }

    const int j    = tid & 31;
    const int head = tid >> 5;
    const int part = (j < 16) ? tid + 16 : tid - 16;
    const float sgn = (j < 16) ? -1.0f : 1.0f;

    #pragma unroll
    for (int r = 0; r < 8; r++) {
        const int row = row0 + r;
        const int b = row >> 8;
        const int s = row & 255;
        float sf, cf;
        sincosf(pa[r], &sf, &cf);
        const float krot = k_s[r][tid] * cf + sgn * k_s[r][part] * sf;
        const int o = ((b * NH + head) * Ss + s) * HD + j;
        g_krot[o] = krot;
        g_v[o]    = va[r];
    }
}

// ---------------------------------------------------------------------------
// Projection kernels: TF32 mma, cp.async double-buffered staging.
// (byte-identical to round 10/12 versions)
// ---------------------------------------------------------------------------
#define QA0  0
#define QA1  2304            // 32*72
#define QW0  4608
#define QW1  13056           // +32*264
#define QTB  21504           // rope tables cos[1024]|sin[1024]
#define QJ_FLOATS 23552
#define QJ_BYTES (QJ_FLOATS * 4)

#define OA0  0
#define OA1  2304            // 64*36
#define OW0  4608
#define OW1  13056
#define OJ_FLOATS 21504
#define OJ_BYTES (OJ_FLOATS * 4)

__global__ void __launch_bounds__(256, 2) qproj_kernel(const float* __restrict__ fv,
                                                       const float* __restrict__ qw,
                                                       const float* __restrict__ qb)
{
    extern __shared__ float sm[];
    const unsigned smu = (unsigned)__cvta_generic_to_shared(sm);
    float* TB = sm + QTB;

    const int tid  = threadIdx.x;
    const int w    = tid >> 5;
    const int lane = tid & 31;
    const int g    = lane >> 2;
    const int tg   = lane & 3;
    const int b    = blockIdx.x >> 9;
    const int n0   = (blockIdx.x & 511) << 6;
    const int mg   = w >> 2;
    const int cg   = w & 3;
    const int m0   = mg * 32;

    // ---- build rope tables (4 sincos per thread) ----
    #pragma unroll
    for (int e = 0; e < 4; e++) {
        const int idx = tid + e * 256;
        const int pos = idx >> 5;
        const int jj  = idx & 31;
        float ex;
        if (jj < 10)      { const int z = jj;      ex = ((z < 5) ? z : z - 5) / 5.0f; }
        else if (jj < 20) { const int y = jj - 10; ex = ((y < 5) ? y : y - 5) / 5.0f; }
        else              { const int x = jj - 20; ex = ((x < 6) ? x : x - 6) / 6.0f; }
        const float invf = expf(-ex * 9.210340371976184f);
        float sf, cf;
        __sincosf((float)pos * invf, &sf, &cf);
        TB[idx]        = cf;
        TB[1024 + idx] = sf;
    }

    const float* __restrict__ fvb = fv + (size_t)b * Cch * Nn;

    float acc[2][8][4];
    #pragma unroll
    for (int mt = 0; mt < 2; mt++)
        #pragma unroll
        for (int nt = 0; nt < 8; nt++)
            #pragma unroll
            for (int i = 0; i < 4; i++) acc[mt][nt][i] = 0.0f;

    // prefetch iteration 0 into buffer 0
    {
        #pragma unroll
        for (int r = 0; r < 2; r++) {
            const int idx = tid + r * 256;
            const int kk = idx >> 4, cc = idx & 15;
            cpasync16(smu + (QA0 + kk * 72 + cc * 4) * 4,
                      fvb + (size_t)kk * Nn + n0 + cc * 4);
        }
        #pragma unroll
        for (int r = 0; r < 8; r++) {
            const int idx = tid + r * 256;
            const int kk = idx >> 6, cc = idx & 63;
            cpasync16(smu + (QW0 + kk * 264 + cc * 4) * 4,
                      qw + (size_t)kk * Cch + cc * 4);
        }
        CP_COMMIT();
    }

    for (int it = 0; it < 8; it++) {
        const int abuf = (it & 1) ? QA1 : QA0;
        const int wbuf = (it & 1) ? QW1 : QW0;
        if (it < 7) {
            const int k1 = (it + 1) * 32;
            const int a2 = (it & 1) ? QA0 : QA1;
            const int w2 = (it & 1) ? QW0 : QW1;
            #pragma unroll
            for (int r = 0; r < 2; r++) {
                const int idx = tid + r * 256;
                const int kk = idx >> 4, cc = idx & 15;
                cpasync16(smu + (a2 + kk * 72 + cc * 4) * 4,
                          fvb + (size_t)(k1 + kk) * Nn + n0 + cc * 4);
            }
            #pragma unroll
            for (int r = 0; r < 8; r++) {
                const int idx = tid + r * 256;
                const int kk = idx >> 6, cc = idx & 63;
                cpasync16(smu + (w2 + kk * 264 + cc * 4) * 4,
                          qw + (size_t)(k1 + kk) * Cch + cc * 4);
            }
            CP_COMMIT();
            CP_WAIT(1);
        } else {
            CP_WAIT(0);
        }
        __syncthreads();

        const float* As = sm + abuf;
        const float* Ws = sm + wbuf;

        unsigned a[2][4][4];
        #pragma unroll
        for (int mt = 0; mt < 2; mt++) {
            const int row = m0 + mt * 16 + g;
            #pragma unroll
            for (int ks = 0; ks < 4; ks++) {
                const int base = ks * 8 + tg;
                a[mt][ks][0] = f2tf(As[base * 72 + row]);
                a[mt][ks][1] = f2tf(As[base * 72 + row + 8]);
                a[mt][ks][2] = f2tf(As[(base + 4) * 72 + row]);
                a[mt][ks][3] = f2tf(As[(base + 4) * 72 + row + 8]);
            }
        }
        #pragma unroll
        for (int nt = 0; nt < 8; nt++) {
            const int c0 = cg * 64 + nt * 8 + g;
            #pragma unroll
            for (int ks = 0; ks < 4; ks++) {
                const unsigned b0 = f2tf(Ws[(ks * 8 + tg) * 264 + c0]);
                const unsigned b1 = f2tf(Ws[(ks * 8 + tg + 4) * 264 + c0]);
                mma8(acc[0][nt], a[0][ks], b0, b1);
                mma8(acc[1][nt], a[1][ks], b0, b1);
            }
        }
        __syncthreads();
    }

    // write accums into OUT[64][258] (overlays staging buffers)
    #pragma unroll
    for (int mt = 0; mt < 2; mt++) {
        const int row = m0 + mt * 16 + g;
        #pragma unroll
        for (int nt = 0; nt < 8; nt++) {
            const int col = cg * 64 + nt * 8 + 2 * tg;
            *(float2*)&sm[row * 258 + col]       = make_float2(acc[mt][nt][0], acc[mt][nt][1]);
            *(float2*)&sm[(row + 8) * 258 + col] = make_float2(acc[mt][nt][2], acc[mt][nt][3]);
        }
    }
    __syncthreads();

    // epilogue: bias + 3D rope via table; thread = channel c for 64 tokens
    const int c    = tid;
    const int j    = c & 31;
    const int head = c >> 5;
    const int sel  = (j < 10) ? 0 : (j < 20) ? 1 : 2;
    const int part  = (j < 16) ? c + 16 : c - 16;
    const float sgn = (j < 16) ? -1.0f : 1.0f;
    const float qbc = qb[c], qbp = qb[part];

    float* __restrict__ qo = g_qrot + (((size_t)(b * NH + head)) * Nn) * HD + j;
    for (int nn = 0; nn < 64; nn++) {
        const int n  = n0 + nn;
        const int dz = n >> 10;
        const int hy = (n >> 5) & 31;
        const int wx = n & 31;
        const int posv = (sel == 0) ? dz : (sel == 1) ? hy : wx;
        const float cf = TB[posv * 32 + j];
        const float sf = TB[1024 + posv * 32 + j];
        const float qv = sm[nn * 258 + c]    + qbc;
        const float pv = sm[nn * 258 + part] + qbp;
        qo[(size_t)n * HD] = qv * cf + sgn * pv * sf;
    }
}

// ---------------------------------------------------------------------------
// Kernel 3: flash attention v4, TF32 mma. CTA = 128 queries (8 warps).
// NEW: two-phase K/V staging (128 keys at a time) halves smem to 72KB
// -> 3 CTAs/SM (24 warps, was 16). 64-key score chunks keep regs <= 85.
// smem: union{Qs[128][36], Ps[128][68]} | Kf[128][36] | Vs[128][40]
// ---------------------------------------------------------------------------
#define APQ  0                       // union: Qs (4608 fl) / Ps (8704 fl)
#define AK   8704
#define AV   (AK + 128*36)           // 13312
#define AT_FLOATS (AV + 128*40)      // 18432
#define AT_BYTES (AT_FLOATS * 4)     // 73728

__global__ void __launch_bounds__(256, 3) attn_kernel()
{
    extern __shared__ float sm[];
    float* Qs = sm + APQ;    // [128][36]  (staging only)
    float* Ps = sm + APQ;    // [128][68]  (after aq-load)
    float* Kf = sm + AK;     // [128][36]
    float* Vs = sm + AV;     // [128][40]

    const int tid  = threadIdx.x;
    const int w    = tid >> 5;       // 0..7
    const int lane = tid & 31;
    const int g    = lane >> 2;
    const int tg   = lane & 3;
    const int n0   = blockIdx.x * 128;
    const int h    = blockIdx.y;
    const int b    = blockIdx.z;
    const size_t bh = (size_t)(b * NH + h);
    const int qr   = w * 16 + g;

    // ---- stage Q (QSCALE + tf32) ----
    {
        const float4* qsrc = (const float4*)(g_qrot + (bh * Nn + n0) * HD);
        #pragma unroll
        for (int r = 0; r < 4; r++) {
            const int idx = tid + r * 256;        // 0..1023
            const float4 f = qsrc[idx];
            const int row = idx >> 3;
            const int c4  = (idx & 7) * 4;
            float4 t;
            t.x = tfval(f.x * QSCALE); t.y = tfval(f.y * QSCALE);
            t.z = tfval(f.z * QSCALE); t.w = tfval(f.w * QSCALE);
            *(float4*)&Qs[row * 36 + c4] = t;
        }
    }
    __syncthreads();

    // ---- load Q a-frags (held for whole kernel) ----
    unsigned aq[4][4];
    #pragma unroll
    for (int ks = 0; ks < 4; ks++) {
        const int base = ks * 8 + tg;
        aq[ks][0] = __float_as_uint(Qs[qr * 36 + base]);
        aq[ks][1] = __float_as_uint(Qs[(qr + 8) * 36 + base]);
        aq[ks][2] = __float_as_uint(Qs[qr * 36 + base + 4]);
        aq[ks][3] = __float_as_uint(Qs[(qr + 8) * 36 + base + 4]);
    }
    __syncthreads();   // Qs dead; Ps may now overlay it

    float m0, m1, l0, l1;
    float o[4][4];
    #pragma unroll
    for (int nt = 0; nt < 4; nt++)
        #pragma unroll
        for (int i = 0; i < 4; i++) o[nt][i] = 0.0f;

    #pragma unroll
    for (int ph = 0; ph < 2; ph++) {
        if (ph) __syncthreads();   // all warps done reading Kf/Vs phase 0

        // ---- stage K/V rows [ph*128, ph*128+128) ----
        {
            const float4* ksrc = (const float4*)(g_krot + (bh * Ss + ph * 128) * HD);
            const float4* vsrc = (const float4*)(g_v    + (bh * Ss + ph * 128) * HD);
            #pragma unroll
            for (int r = 0; r < 4; r++) {
                const int idx = tid + r * 256;    // 0..1023
                const int key = idx >> 3;
                const int c4  = (idx & 7) * 4;
                const float4 fk = ksrc[idx];
                float4 tk;
                tk.x = tfval(fk.x); tk.y = tfval(fk.y); tk.z = tfval(fk.z); tk.w = tfval(fk.w);
                *(float4*)&Kf[key * 36 + c4] = tk;
                const float4 fv4 = vsrc[idx];
                float4 tv;
                tv.x = tfval(fv4.x); tv.y = tfval(fv4.y); tv.z = tfval(fv4.z); tv.w = tfval(fv4.w);
                *(float4*)&Vs[key * 40 + c4] = tv;
            }
        }
        __syncthreads();

        #pragma unroll
        for (int ch = 0; ch < 2; ch++) {
            // ---- QK^T for 64-key chunk (scores in log2 units) ----
            float c[8][4];
            #pragma unroll
            for (int nt = 0; nt < 8; nt++)
                #pragma unroll
                for (int i = 0; i < 4; i++) c[nt][i] = 0.0f;

            #pragma unroll
            for (int nt = 0; nt < 8; nt++) {
                const int k0 = ch * 64 + nt * 8 + g;   // local key row
                #pragma unroll
                for (int ks = 0; ks < 4; ks++) {
                    const unsigned b0 = __float_as_uint(Kf[k0 * 36 + ks * 8 + tg]);
                    const unsigned b1 = __float_as_uint(Kf[k0 * 36 + ks * 8 + tg + 4]);
                    mma8(c[nt], aq[ks], b0, b1);
                }
            }

            // ---- chunk row max ----
            float cm0 = -1e30f, cm1 = -1e30f;
            #pragma unroll
            for (int nt = 0; nt < 8; nt++) {
                cm0 = fmaxf(cm0, fmaxf(c[nt][0], c[nt][1]));
                cm1 = fmaxf(cm1, fmaxf(c[nt][2], c[nt][3]));
            }
            cm0 = fmaxf(cm0, __shfl_xor_sync(0xffffffffu, cm0, 1));
            cm0 = fmaxf(cm0, __shfl_xor_sync(0xffffffffu, cm0, 2));
            cm1 = fmaxf(cm1, __shfl_xor_sync(0xffffffffu, cm1, 1));
            cm1 = fmaxf(cm1, __shfl_xor_sync(0xffffffffu, cm1, 2));

            float sc0 = 1.0f, sc1 = 1.0f;
            if (ph == 0 && ch == 0) {
                m0 = cm0; m1 = cm1;
            } else {
                const float mn0 = fmaxf(m0, cm0);
                const float mn1 = fmaxf(m1, cm1);
                sc0 = exp2f(m0 - mn0);
                sc1 = exp2f(m1 - mn1);
                m0 = mn0; m1 = mn1;
            }

            // ---- exp2 + row sums (probs kept as raw fp32 -> tf32-trunc) ----
            float s0 = 0.0f, s1 = 0.0f;
            #pragma unroll
            for (int nt = 0; nt < 8; nt++) {
                const float p0 = exp2f(c[nt][0] - m0);
                const float p1 = exp2f(c[nt][1] - m0);
                const float p2 = exp2f(c[nt][2] - m1);
                const float p3 = exp2f(c[nt][3] - m1);
                s0 += p0 + p1;  s1 += p2 + p3;
                c[nt][0] = p0; c[nt][1] = p1; c[nt][2] = p2; c[nt][3] = p3;
            }
            s0 += __shfl_xor_sync(0xffffffffu, s0, 1);
            s0 += __shfl_xor_sync(0xffffffffu, s0, 2);
            s1 += __shfl_xor_sync(0xffffffffu, s1, 1);
            s1 += __shfl_xor_sync(0xffffffffu, s1, 2);
            if (ph == 0 && ch == 0) {
                l0 = s0;  l1 = s1;
            } else {
                l0 = l0 * sc0 + s0;
                l1 = l1 * sc1 + s1;
                #pragma unroll
                for (int nt = 0; nt < 4; nt++) {
                    o[nt][0] *= sc0;  o[nt][1] *= sc0;
                    o[nt][2] *= sc1;  o[nt][3] *= sc1;
                }
            }

            // ---- write chunk probs to per-warp Ps rows ----
            #pragma unroll
            for (int nt = 0; nt < 8; nt++) {
                *(float2*)&Ps[qr * 68 + nt * 8 + 2 * tg]       = make_float2(c[nt][0], c[nt][1]);
                *(float2*)&Ps[(qr + 8) * 68 + nt * 8 + 2 * tg] = make_float2(c[nt][2], c[nt][3]);
            }
            __syncwarp();

            // ---- P @ V for this chunk ----
            #pragma unroll
            for (int s = 0; s < 8; s++) {
                unsigned a[4];
                a[0] = __float_as_uint(Ps[qr * 68 + s * 8 + tg]);
                a[1] = __float_as_uint(Ps[(qr + 8) * 68 + s * 8 + tg]);
                a[2] = __float_as_uint(Ps[qr * 68 + s * 8 + tg + 4]);
                a[3] = __float_as_uint(Ps[(qr + 8) * 68 + s * 8 + tg + 4]);
                const int kk = ch * 64 + s * 8;   // local key row
                #pragma unroll
                for (int nt3 = 0; nt3 < 4; nt3++) {
                    const unsigned b0 = __float_as_uint(Vs[(kk + tg) * 40 + nt3 * 8 + g]);
                    const unsigned b1 = __float_as_uint(Vs[(kk + tg + 4) * 40 + nt3 * 8 + g]);
                    mma8(o[nt3], a, b0, b1);
                }
            }
            __syncwarp();
        }
    }

    // ---- epilogue: normalize + store ----
    const float r0 = 1.0f / l0;
    const float r1 = 1.0f / l1;
    #pragma unroll
    for (int nt = 0; nt < 4; nt++) {
        const int hd = nt * 8 + 2 * tg;
        float* p0 = g_att + ((size_t)(b * Nn + n0 + qr)) * Cch + h * HD + hd;
        float* p1 = g_att + ((size_t)(b * Nn + n0 + qr + 8)) * Cch + h * HD + hd;
        *(float2*)p0 = make_float2(o[nt][0] * r0, o[nt][1] * r0);
        *(float2*)p1 = make_float2(o[nt][2] * r1, o[nt][3] * r1);
    }
}

// ---------------------------------------------------------------------------
// Kernel 4: O projection + transpose, TF32 mma, cp.async double-buffered.
// ---------------------------------------------------------------------------
__global__ void __launch_bounds__(256, 2) oproj_kernel(const float* __restrict__ ow,
                                                       const float* __restrict__ ob,
                                                       float* __restrict__ out)
{
    extern __shared__ float sm[];
    const unsigned smu = (unsigned)__cvta_generic_to_shared(sm);

    const int tid  = threadIdx.x;
    const int w    = tid >> 5;
    const int lane = tid & 31;
    const int g    = lane >> 2;
    const int tg   = lane & 3;
    const int b    = blockIdx.x >> 9;
    const int n0   = (blockIdx.x & 511) << 6;
    const int mg   = w >> 2;
    const int cg   = w & 3;
    const int m0   = mg * 32;

    const float* __restrict__ att = g_att + ((size_t)(b * Nn + n0)) * Cch;

    float acc[2][8][4];
    #pragma unroll
    for (int mt = 0; mt < 2; mt++)
        #pragma unroll
        for (int nt = 0; nt < 8; nt++)
            #pragma unroll
            for (int i = 0; i < 4; i++) acc[mt][nt][i] = 0.0f;

    // prefetch iter 0 into buffer 0
    {
        #pragma unroll
        for (int r = 0; r < 2; r++) {
            const int idx = tid + r * 256;       // 0..511
            const int nn = idx >> 3, cc = idx & 7;
            cpasync16(smu + (OA0 + nn * 36 + cc * 4) * 4,
                      att + (size_t)nn * Cch + cc * 4);
        }
        #pragma unroll
        for (int r = 0; r < 8; r++) {
            const int idx = tid + r * 256;
            const int kk = idx >> 6, cc = idx & 63;
            cpasync16(smu + (OW0 + kk * 264 + cc * 4) * 4,
                      ow + (size_t)kk * Cch + cc * 4);
        }
        CP_COMMIT();
    }

    for (int it = 0; it < 8; it++) {
        const int abuf = (it & 1) ? OA1 : OA0;
        const int wbuf = (it & 1) ? OW1 : OW0;
        if (it < 7) {
            const int k1 = (it + 1) * 32;
            const int a2 = (it & 1) ? OA0 : OA1;
            const int w2 = (it & 1) ? OW0 : OW1;
            #pragma unroll
            for (int r = 0; r < 2; r++) {
                const int idx = tid + r * 256;
                const int nn = idx >> 3, cc = idx & 7;
                cpasync16(smu + (a2 + nn * 36 + cc * 4) * 4,
                          att + (size_t)nn * Cch + k1 + cc * 4);
            }
            #pragma unroll
            for (int r = 0; r < 8; r++) {
                const int idx = tid + r * 256;
                const int kk = idx >> 6, cc = idx & 63;
                cpasync16(smu + (w2 + kk * 264 + cc * 4) * 4,
                          ow + (size_t)(k1 + kk) * Cch + cc * 4);
            }
            CP_COMMIT();
            CP_WAIT(1);
        } else {
            CP_WAIT(0);
        }
        __syncthreads();

        const float* As = sm + abuf;
        const float* Ws = sm + wbuf;

        unsigned a[2][4][4];
        #pragma unroll
        for (int mt = 0; mt < 2; mt++) {
            const int row = m0 + mt * 16 + g;
            #pragma unroll
            for (int ks = 0; ks < 4; ks++) {
                const int base = ks * 8 + tg;
                a[mt][ks][0] = f2tf(As[row * 36 + base]);
                a[mt][ks][1] = f2tf(As[(row + 8) * 36 + base]);
                a[mt][ks][2] = f2tf(As[row * 36 + base + 4]);
                a[mt][ks][3] = f2tf(As[(row + 8) * 36 + base + 4]);
            }
        }
        #pragma unroll
        for (int nt = 0; nt < 8; nt++) {
            const int c0 = cg * 64 + nt * 8 + g;
            #pragma unroll
            for (int ks = 0; ks < 4; ks++) {
                const unsigned b0 = f2tf(Ws[(ks * 8 + tg) * 264 + c0]);
                const unsigned b1 = f2tf(Ws[(ks * 8 + tg + 4) * 264 + c0]);
                mma8(acc[0][nt], a[0][ks], b0, b1);
                mma8(acc[1][nt], a[1][ks], b0, b1);
            }
        }
        __syncthreads();
    }

    #pragma unroll
    for (int mt = 0; mt < 2; mt++) {
        const int row = m0 + mt * 16 + g;
        #pragma unroll
        for (int nt = 0; nt < 8; nt++) {
            const int col = cg * 64 + nt * 8 + 2 * tg;
            *(float2*)&sm[row * 258 + col]       = make_float2(acc[mt][nt][0], acc[mt][nt][1]);
            *(float2*)&sm[(row + 8) * 258 + col] = make_float2(acc[mt][nt][2], acc[mt][nt][3]);
        }
    }
    __syncthreads();

    // transposed coalesced store: out[b][c][n0 + token]
    const int grp = tid >> 5;
    float* __restrict__ obp = out + (size_t)b * Cch * Nn + n0 + lane;
    #pragma unroll 4
    for (int it = 0; it < 32; it++) {
        const int c = it * 8 + grp;
        const float bias = ob[c];
        obp[(size_t)c * Nn]      = sm[lane * 258 + c] + bias;
        obp[(size_t)c * Nn + 32] = sm[(lane + 32) * 258 + c] + bias;
    }
}

// ---------------------------------------------------------------------------
extern "C" void kernel_launch(void* const* d_in, const int* in_sizes, int n_in,
                              void* d_out, int out_size)
{
    const float* fused_visual = (const float*)d_in[0];
    const float* text_emb     = (const float*)d_in[1];
    const float* q_w = (const float*)d_in[2];
    const float* q_b = (const float*)d_in[3];
    const float* k_w = (const float*)d_in[4];
    const float* k_b = (const float*)d_in[5];
    const float* v_w = (const float*)d_in[6];
    const float* v_b = (const float*)d_in[7];
    const float* o_w = (const float*)d_in[8];
    const float* o_b = (const float*)d_in[9];
    const float* m1_w = (const float*)d_in[10];
    const float* m1_b = (const float*)d_in[11];
    const float* m2_w = (const float*)d_in[12];
    const float* m2_b = (const float*)d_in[13];
    float* out = (float*)d_out;

    static int smem_ok = -1;
    if (smem_ok < 0) {
        cudaFuncSetAttribute(attn_kernel,  cudaFuncAttributeMaxDynamicSharedMemorySize, AT_BYTES);
        cudaFuncSetAttribute(qproj_kernel, cudaFuncAttributeMaxDynamicSharedMemorySize, QJ_BYTES);
        cudaFuncSetAttribute(oproj_kernel, cudaFuncAttributeMaxDynamicSharedMemorySize, OJ_BYTES);
        smem_ok = 1;
    }

    text_kernel<<<(Bv * Ss) / 8, 256>>>(text_emb, k_w, k_b, v_w, v_b, m1_w, m1_b, m2_w, m2_b);
    qproj_kernel<<<Bv * (Nn / 64), 256, QJ_BYTES>>>(fused_visual, q_w, q_b);
    attn_kernel<<<dim3(Nn / 128, NH, Bv), 256, AT_BYTES>>>();
    oproj_kernel<<<Bv * (Nn / 64), 256, OJ_BYTES>>>(o_w, o_b, out);
}

// round 14
// speedup vs baseline: 1.2654x; 1.2654x over previous
#include <cuda_runtime.h>
#include <cuda_fp16.h>
#include <math.h>

// ---------------- problem constants ----------------
#define Bv   2
#define Cch  256
#define Nn   32768           // D*H*W
#define Ss   256
#define TDd  512
#define NH   8
#define HD   32
#define QSCALE 0.2550396392825023f    // 32^-0.5 * log2(e)

// ---------------- scratch ----------------
__device__ __half g_krotH[Bv * NH * Ss * HD];          // [b,h,s,hd]
__device__ __half g_vT   [Bv * NH * HD * Ss];          // [b,h,hd,s]  (transposed)
__device__ __half g_qrotH[(size_t)Bv * NH * Nn * HD];  // [b,h,n,hd]  32MB, pre-scaled
__device__ __half g_attH [(size_t)Bv * Nn * Cch];      // [b,n,c]     32MB
__device__ __half g_owT  [Cch * Cch];                  // o_w transposed [c][k] fp16

// ---------------- helpers ----------------
__device__ __forceinline__ unsigned f2tf(float x) {
    unsigned u;
    asm("cvt.rna.tf32.f32 %0, %1;" : "=r"(u) : "f"(x));
    return u;
}

__device__ __forceinline__ void mma8(float c[4], const unsigned a[4],
                                     unsigned b0, unsigned b1) {
    asm volatile(
        "mma.sync.aligned.m16n8k8.row.col.f32.tf32.tf32.f32 "
        "{%0,%1,%2,%3},{%4,%5,%6,%7},{%8,%9},{%0,%1,%2,%3};"
        : "+f"(c[0]), "+f"(c[1]), "+f"(c[2]), "+f"(c[3])
        : "r"(a[0]), "r"(a[1]), "r"(a[2]), "r"(a[3]), "r"(b0), "r"(b1));
}

__device__ __forceinline__ void mma16(float c[4], const unsigned a[4],
                                      unsigned b0, unsigned b1) {
    asm volatile(
        "mma.sync.aligned.m16n8k16.row.col.f32.f16.f16.f32 "
        "{%0,%1,%2,%3},{%4,%5,%6,%7},{%8,%9},{%0,%1,%2,%3};"
        : "+f"(c[0]), "+f"(c[1]), "+f"(c[2]), "+f"(c[3])
        : "r"(a[0]), "r"(a[1]), "r"(a[2]), "r"(a[3]), "r"(b0), "r"(b1));
}

__device__ __forceinline__ void cpasync16(unsigned dst, const void* src) {
    asm volatile("cp.async.ca.shared.global [%0], [%1], 16;" :: "r"(dst), "l"(src));
}
#define CP_COMMIT()  asm volatile("cp.async.commit_group;")
#define CP_WAIT(n)   asm volatile("cp.async.wait_group %0;" :: "n"(n))

// ---------------------------------------------------------------------------
// Kernel 0: transpose o_w [k][c] fp32 -> g_owT [c][k] fp16. 64 CTAs, tiny.
// ---------------------------------------------------------------------------
__global__ void owt_kernel(const float* __restrict__ ow)
{
    __shared__ float t[32][33];
    const int tx = threadIdx.x & 31;
    const int ty = threadIdx.x >> 5;           // 0..7
    const int c0 = (blockIdx.x & 7) * 32;
    const int k0 = (blockIdx.x >> 3) * 32;
    #pragma unroll
    for (int r = ty; r < 32; r += 8)
        t[r][tx] = ow[(size_t)(k0 + r) * Cch + c0 + tx];
    __syncthreads();
    #pragma unroll
    for (int r = ty; r < 32; r += 8)
        g_owT[(size_t)(c0 + r) * Cch + k0 + tx] = __float2half(t[tx][r]);
}

// ---------------------------------------------------------------------------
// Kernel 1: text side (K/V proj, MLP phase, rope on K). 64 CTAs, tiny. FFMA.
// Writes K rotated as fp16 [s][hd] and V as fp16 TRANSPOSED [hd][s].
// ---------------------------------------------------------------------------
__global__ void text_kernel(const float* __restrict__ text,
                            const float* __restrict__ k_w, const float* __restrict__ k_b,
                            const float* __restrict__ v_w, const float* __restrict__ v_b,
                            const float* __restrict__ m1_w, const float* __restrict__ m1_b,
                            const float* __restrict__ m2_w, const float* __restrict__ m2_b)
{
    __shared__ float t_s[8][TDd];
    __shared__ float h_s[8][Cch];
    __shared__ float k_s[8][Cch];

    const int tid  = threadIdx.x;
    const int row0 = blockIdx.x * 8;

    #pragma unroll
    for (int r = 0; r < 8; r++) {
        t_s[r][tid]       = text[(size_t)(row0 + r) * TDd + tid];
        t_s[r][tid + 256] = text[(size_t)(row0 + r) * TDd + tid + 256];
    }
    __syncthreads();

    float ka[8], va[8], ha[8];
    #pragma unroll
    for (int r = 0; r < 8; r++) { ka[r] = k_b[tid]; va[r] = v_b[tid]; ha[r] = m1_b[tid]; }

    for (int i = 0; i < TDd; i++) {
        const float wk = k_w[i * Cch + tid];
        const float wv = v_w[i * Cch + tid];
        const float wm = m1_w[i * Cch + tid];
        #pragma unroll
        for (int r = 0; r < 8; r++) {
            const float t = t_s[r][i];
            ka[r] += t * wk;  va[r] += t * wv;  ha[r] += t * wm;
        }
    }

    #pragma unroll
    for (int r = 0; r < 8; r++) {
        const float x = ha[r];
        h_s[r][tid] = 0.5f * x * (1.0f + erff(x * 0.7071067811865475f));
        k_s[r][tid] = ka[r];
    }
    __syncthreads();

    float pa[8];
    #pragma unroll
    for (int r = 0; r < 8; r++) pa[r] = m2_b[tid];
    for (int i = 0; i < Cch; i++) {
        const float wm2 = m2_w[i * Cch + tid];
        #pragma unroll
        for (int r = 0; r < 8; r++) pa[r] += h_s[r][i] * wm2;
    }

    const int j    = tid & 31;
    const int head = tid >> 5;
    const int part = (j < 16) ? tid + 16 : tid - 16;
    const float sgn = (j < 16) ? -1.0f : 1.0f;

    #pragma unroll
    for (int r = 0; r < 8; r++) {
        const int row = row0 + r;
        const int b = row >> 8;
        const int s = row & 255;
        float sf, cf;
        sincosf(pa[r], &sf, &cf);
        const float krot = k_s[r][tid] * cf + sgn * k_s[r][part] * sf;
        const int bh = b * NH + head;
        g_krotH[(bh * Ss + s) * HD + j]  = __float2half(krot);
        g_vT  [(bh * HD + j) * Ss + s]   = __float2half(va[r]);
    }
}

// ---------------------------------------------------------------------------
// Kernel 2: Q projection (tf32 mainloop, unchanged) + rope epilogue emitting
// fp16 pre-scaled by QSCALE into g_qrotH.
// ---------------------------------------------------------------------------
#define QA0  0
#define QA1  2304            // 32*72
#define QW0  4608
#define QW1  13056           // +32*264
#define QTB  21504           // rope tables cos[1024]|sin[1024]
#define QJ_FLOATS 23552
#define QJ_BYTES (QJ_FLOATS * 4)

__global__ void __launch_bounds__(256, 2) qproj_kernel(const float* __restrict__ fv,
                                                       const float* __restrict__ qw,
                                                       const float* __restrict__ qb)
{
    extern __shared__ float sm[];
    const unsigned smu = (unsigned)__cvta_generic_to_shared(sm);
    float* TB = sm + QTB;

    const int tid  = threadIdx.x;
    const int w    = tid >> 5;
    const int lane = tid & 31;
    const int g    = lane >> 2;
    const int tg   = lane & 3;
    const int b    = blockIdx.x >> 9;
    const int n0   = (blockIdx.x & 511) << 6;
    const int mg   = w >> 2;
    const int cg   = w & 3;
    const int m0   = mg * 32;

    #pragma unroll
    for (int e = 0; e < 4; e++) {
        const int idx = tid + e * 256;
        const int pos = idx >> 5;
        const int jj  = idx & 31;
        float ex;
        if (jj < 10)      { const int z = jj;      ex = ((z < 5) ? z : z - 5) / 5.0f; }
        else if (jj < 20) { const int y = jj - 10; ex = ((y < 5) ? y : y - 5) / 5.0f; }
        else              { const int x = jj - 20; ex = ((x < 6) ? x : x - 6) / 6.0f; }
        const float invf = expf(-ex * 9.210340371976184f);
        float sf, cf;
        __sincosf((float)pos * invf, &sf, &cf);
        TB[idx]        = cf;
        TB[1024 + idx] = sf;
    }

    const float* __restrict__ fvb = fv + (size_t)b * Cch * Nn;

    float acc[2][8][4];
    #pragma unroll
    for (int mt = 0; mt < 2; mt++)
        #pragma unroll
        for (int nt = 0; nt < 8; nt++)
            #pragma unroll
            for (int i = 0; i < 4; i++) acc[mt][nt][i] = 0.0f;

    {
        #pragma unroll
        for (int r = 0; r < 2; r++) {
            const int idx = tid + r * 256;
            const int kk = idx >> 4, cc = idx & 15;
            cpasync16(smu + (QA0 + kk * 72 + cc * 4) * 4,
                      fvb + (size_t)kk * Nn + n0 + cc * 4);
        }
        #pragma unroll
        for (int r = 0; r < 8; r++) {
            const int idx = tid + r * 256;
            const int kk = idx >> 6, cc = idx & 63;
            cpasync16(smu + (QW0 + kk * 264 + cc * 4) * 4,
                      qw + (size_t)kk * Cch + cc * 4);
        }
        CP_COMMIT();
    }

    for (int it = 0; it < 8; it++) {
        const int abuf = (it & 1) ? QA1 : QA0;
        const int wbuf = (it & 1) ? QW1 : QW0;
        if (it < 7) {
            const int k1 = (it + 1) * 32;
            const int a2 = (it & 1) ? QA0 : QA1;
            const int w2 = (it & 1) ? QW0 : QW1;
            #pragma unroll
            for (int r = 0; r < 2; r++) {
                const int idx = tid + r * 256;
                const int kk = idx >> 4, cc = idx & 15;
                cpasync16(smu + (a2 + kk * 72 + cc * 4) * 4,
                          fvb + (size_t)(k1 + kk) * Nn + n0 + cc * 4);
            }
            #pragma unroll
            for (int r = 0; r < 8; r++) {
                const int idx = tid + r * 256;
                const int kk = idx >> 6, cc = idx & 63;
                cpasync16(smu + (w2 + kk * 264 + cc * 4) * 4,
                          qw + (size_t)(k1 + kk) * Cch + cc * 4);
            }
            CP_COMMIT();
            CP_WAIT(1);
        } else {
            CP_WAIT(0);
        }
        __syncthreads();

        const float* As = sm + abuf;
        const float* Ws = sm + wbuf;

        unsigned a[2][4][4];
        #pragma unroll
        for (int mt = 0; mt < 2; mt++) {
            const int row = m0 + mt * 16 + g;
            #pragma unroll
            for (int ks = 0; ks < 4; ks++) {
                const int base = ks * 8 + tg;
                a[mt][ks][0] = f2tf(As[base * 72 + row]);
                a[mt][ks][1] = f2tf(As[base * 72 + row + 8]);
                a[mt][ks][2] = f2tf(As[(base + 4) * 72 + row]);
                a[mt][ks][3] = f2tf(As[(base + 4) * 72 + row + 8]);
            }
        }
        #pragma unroll
        for (int nt = 0; nt < 8; nt++) {
            const int c0 = cg * 64 + nt * 8 + g;
            #pragma unroll
            for (int ks = 0; ks < 4; ks++) {
                const unsigned b0 = f2tf(Ws[(ks * 8 + tg) * 264 + c0]);
                const unsigned b1 = f2tf(Ws[(ks * 8 + tg + 4) * 264 + c0]);
                mma8(acc[0][nt], a[0][ks], b0, b1);
                mma8(acc[1][nt], a[1][ks], b0, b1);
            }
        }
        __syncthreads();
    }

    #pragma unroll
    for (int mt = 0; mt < 2; mt++) {
        const int row = m0 + mt * 16 + g;
        #pragma unroll
        for (int nt = 0; nt < 8; nt++) {
            const int col = cg * 64 + nt * 8 + 2 * tg;
            *(float2*)&sm[row * 258 + col]       = make_float2(acc[mt][nt][0], acc[mt][nt][1]);
            *(float2*)&sm[(row + 8) * 258 + col] = make_float2(acc[mt][nt][2], acc[mt][nt][3]);
        }
    }
    __syncthreads();

    // epilogue: bias + 3D rope + QSCALE, write fp16
    const int c    = tid;
    const int j    = c & 31;
    const int head = c >> 5;
    const int sel  = (j < 10) ? 0 : (j < 20) ? 1 : 2;
    const int part  = (j < 16) ? c + 16 : c - 16;
    const float sgn = (j < 16) ? -1.0f : 1.0f;
    const float qbc = qb[c], qbp = qb[part];

    __half* __restrict__ qo = g_qrotH + (((size_t)(b * NH + head)) * Nn) * HD + j;
    for (int nn = 0; nn < 64; nn++) {
        const int n  = n0 + nn;
        const int dz = n >> 10;
        const int hy = (n >> 5) & 31;
        const int wx = n & 31;
        const int posv = (sel == 0) ? dz : (sel == 1) ? hy : wx;
        const float cf = TB[posv * 32 + j];
        const float sf = TB[1024 + posv * 32 + j];
        const float qv = sm[nn * 258 + c]    + qbc;
        const float pv = sm[nn * 258 + part] + qbp;
        qo[(size_t)n * HD] = __float2half((qv * cf + sgn * pv * sf) * QSCALE);
    }
}

// ---------------------------------------------------------------------------
// Kernel 3: flash attention, FP16 m16n8k16. CTA = 128 queries (8 warps).
// smem (halves): union{Qs[128][40], Ps[128][72]} | Kf[256][40] | Vt[32][264]
// = 55.8KB -> 3 CTAs/SM. All fragment LDS bank-conflict-free by stride.
// ---------------------------------------------------------------------------
#define AQS  0                       // Qs 5120 halves / Ps 9216 halves (union)
#define AKF  9216
#define AVT  (AKF + 256*40)          // 19456
#define AT_HALVES (AVT + 32*264)     // 27904
#define AT_BYTES (AT_HALVES * 2)     // 55808

__global__ void __launch_bounds__(256, 3) attn_kernel()
{
    extern __shared__ __half smh[];
    const unsigned smu = (unsigned)__cvta_generic_to_shared(smh);

    const int tid  = threadIdx.x;
    const int w    = tid >> 5;       // 0..7
    const int lane = tid & 31;
    const int g    = lane >> 2;
    const int tg   = lane & 3;
    const int n0   = blockIdx.x * 128;
    const int h    = blockIdx.y;
    const int b    = blockIdx.z;
    const size_t bh = (size_t)(b * NH + h);
    const int qr   = w * 16 + g;

    // ---- stage Q, K, Vt via cp.async (all fp16, k-contiguous) ----
    {
        #pragma unroll
        for (int r = 0; r < 2; r++) {            // Q: 128 rows x 64B
            const int idx = tid + r * 256;
            const int row = idx >> 2, cc = idx & 3;
            cpasync16(smu + (AQS + row * 40) * 2 + cc * 16,
                      g_qrotH + (bh * Nn + n0 + row) * HD + cc * 8);
        }
        #pragma unroll
        for (int r = 0; r < 4; r++) {            // K: 256 rows x 64B
            const int idx = tid + r * 256;
            const int row = idx >> 2, cc = idx & 3;
            cpasync16(smu + (AKF + row * 40) * 2 + cc * 16,
                      g_krotH + (bh * Ss + row) * HD + cc * 8);
        }
        #pragma unroll
        for (int r = 0; r < 4; r++) {            // Vt: 32 rows x 512B
            const int idx = tid + r * 256;
            const int row = idx >> 5, cc = idx & 31;
            cpasync16(smu + (AVT + row * 264) * 2 + cc * 16,
                      g_vT + (bh * HD + row) * Ss + cc * 8);
        }
        CP_COMMIT();
        CP_WAIT(0);
    }
    __syncthreads();

    // ---- Q a-frags (HD=32 -> 2 k-steps of 16) ----
    unsigned aq[2][4];
    #pragma unroll
    for (int ks = 0; ks < 2; ks++) {
        const int kb = ks * 16 + 2 * tg;
        aq[ks][0] = *(const unsigned*)&smh[AQS + qr * 40 + kb];
        aq[ks][1] = *(const unsigned*)&smh[AQS + (qr + 8) * 40 + kb];
        aq[ks][2] = *(const unsigned*)&smh[AQS + qr * 40 + kb + 8];
        aq[ks][3] = *(const unsigned*)&smh[AQS + (qr + 8) * 40 + kb + 8];
    }
    __syncthreads();   // Qs dead; Ps overlays it

    float m0, m1, l0, l1;
    float o[4][4];
    #pragma unroll
    for (int nt = 0; nt < 4; nt++)
        #pragma unroll
        for (int i = 0; i < 4; i++) o[nt][i] = 0.0f;

    #pragma unroll
    for (int ch = 0; ch < 4; ch++) {
        // ---- QK^T for 64-key chunk (log2-scaled scores) ----
        float c[8][4];
        #pragma unroll
        for (int nt = 0; nt < 8; nt++)
            #pragma unroll
            for (int i = 0; i < 4; i++) c[nt][i] = 0.0f;

        #pragma unroll
        for (int nt = 0; nt < 8; nt++) {
            const int key = ch * 64 + nt * 8 + g;
            #pragma unroll
            for (int ks = 0; ks < 2; ks++) {
                const int kb = ks * 16 + 2 * tg;
                const unsigned b0 = *(const unsigned*)&smh[AKF + key * 40 + kb];
                const unsigned b1 = *(const unsigned*)&smh[AKF + key * 40 + kb + 8];
                mma16(c[nt], aq[ks], b0, b1);
            }
        }

        // ---- chunk row max ----
        float cm0 = -1e30f, cm1 = -1e30f;
        #pragma unroll
        for (int nt = 0; nt < 8; nt++) {
            cm0 = fmaxf(cm0, fmaxf(c[nt][0], c[nt][1]));
            cm1 = fmaxf(cm1, fmaxf(c[nt][2], c[nt][3]));
        }
        cm0 = fmaxf(cm0, __shfl_xor_sync(0xffffffffu, cm0, 1));
        cm0 = fmaxf(cm0, __shfl_xor_sync(0xffffffffu, cm0, 2));
        cm1 = fmaxf(cm1, __shfl_xor_sync(0xffffffffu, cm1, 1));
        cm1 = fmaxf(cm1, __shfl_xor_sync(0xffffffffu, cm1, 2));

        float sc0 = 1.0f, sc1 = 1.0f;
        if (ch == 0) {
            m0 = cm0; m1 = cm1;
        } else {
            const float mn0 = fmaxf(m0, cm0);
            const float mn1 = fmaxf(m1, cm1);
            sc0 = exp2f(m0 - mn0);
            sc1 = exp2f(m1 - mn1);
            m0 = mn0; m1 = mn1;
        }

        // ---- exp2 + row sums (fp32), pack probs fp16 into Ps ----
        float s0 = 0.0f, s1 = 0.0f;
        #pragma unroll
        for (int nt = 0; nt < 8; nt++) {
            const float p0 = exp2f(c[nt][0] - m0);
            const float p1 = exp2f(c[nt][1] - m0);
            const float p2 = exp2f(c[nt][2] - m1);
            const float p3 = exp2f(c[nt][3] - m1);
            s0 += p0 + p1;  s1 += p2 + p3;
            *(__half2*)&smh[AQS + qr * 72 + nt * 8 + 2 * tg]       = __floats2half2_rn(p0, p1);
            *(__half2*)&smh[AQS + (qr + 8) * 72 + nt * 8 + 2 * tg] = __floats2half2_rn(p2, p3);
        }
        s0 += __shfl_xor_sync(0xffffffffu, s0, 1);
        s0 += __shfl_xor_sync(0xffffffffu, s0, 2);
        s1 += __shfl_xor_sync(0xffffffffu, s1, 1);
        s1 += __shfl_xor_sync(0xffffffffu, s1, 2);
        if (ch == 0) {
            l0 = s0;  l1 = s1;
        } else {
            l0 = l0 * sc0 + s0;
            l1 = l1 * sc1 + s1;
            #pragma unroll
            for (int nt = 0; nt < 4; nt++) {
                o[nt][0] *= sc0;  o[nt][1] *= sc0;
                o[nt][2] *= sc1;  o[nt][3] *= sc1;
            }
        }
        __syncwarp();

        // ---- P @ V for this chunk (k = 64 keys -> 4 k-steps of 16) ----
        #pragma unroll
        for (int ss = 0; ss < 4; ss++) {
            const int sb = ss * 16 + 2 * tg;
            unsigned a[4];
            a[0] = *(const unsigned*)&smh[AQS + qr * 72 + sb];
            a[1] = *(const unsigned*)&smh[AQS + (qr + 8) * 72 + sb];
            a[2] = *(const unsigned*)&smh[AQS + qr * 72 + sb + 8];
            a[3] = *(const unsigned*)&smh[AQS + (qr + 8) * 72 + sb + 8];
            const int s0i = ch * 64 + ss * 16 + 2 * tg;
            #pragma unroll
            for (int nt = 0; nt < 4; nt++) {
                const int hd = nt * 8 + g;
                const unsigned b0 = *(const unsigned*)&smh[AVT + hd * 264 + s0i];
                const unsigned b1 = *(const unsigned*)&smh[AVT + hd * 264 + s0i + 8];
                mma16(o[nt], a, b0, b1);
            }
        }
        __syncwarp();
    }

    // ---- epilogue: normalize + fp16 store ----
    const float r0 = 1.0f / l0;
    const float r1 = 1.0f / l1;
    #pragma unroll
    for (int nt = 0; nt < 4; nt++) {
        const int hd = nt * 8 + 2 * tg;
        __half* p0 = g_attH + ((size_t)(b * Nn + n0 + qr)) * Cch + h * HD + hd;
        __half* p1 = g_attH + ((size_t)(b * Nn + n0 + qr + 8)) * Cch + h * HD + hd;
        *(__half2*)p0 = __floats2half2_rn(o[nt][0] * r0, o[nt][1] * r0);
        *(__half2*)p1 = __floats2half2_rn(o[nt][2] * r1, o[nt][3] * r1);
    }
}

// ---------------------------------------------------------------------------
// Kernel 4: O projection + transpose, FP16 m16n8k16, cp.async double-buffered.
// smem halves: As0[64][40] As1 | Wt0[256][40] Wt1  (25600 halves = 51.2KB)
// overlaid by OUT fp32 [64][258] (66KB) for the epilogue -> OJ_BYTES 66KB.
// ---------------------------------------------------------------------------
#define HA0  0
#define HA1  2560            // 64*40
#define HW0  5120
#define HW1  15360           // +256*40
#define OJ_BYTES (16512 * 4) // OUT 64x258 fp32 dominates

__global__ void __launch_bounds__(256, 2) oproj_kernel(const float* __restrict__ ob,
                                                       float* __restrict__ out)
{
    extern __shared__ float sm[];
    __half* smh = (__half*)sm;
    const unsigned smu = (unsigned)__cvta_generic_to_shared(sm);

    const int tid  = threadIdx.x;
    const int w    = tid >> 5;
    const int lane = tid & 31;
    const int g    = lane >> 2;
    const int tg   = lane & 3;
    const int b    = blockIdx.x >> 9;
    const int n0   = (blockIdx.x & 511) << 6;
    const int mg   = w >> 2;
    const int cg   = w & 3;
    const int m0   = mg * 32;

    const __half* __restrict__ att = g_attH + ((size_t)(b * Nn + n0)) * Cch;

    float acc[2][8][4];
    #pragma unroll
    for (int mt = 0; mt < 2; mt++)
        #pragma unroll
        for (int nt = 0; nt < 8; nt++)
            #pragma unroll
            for (int i = 0; i < 4; i++) acc[mt][nt][i] = 0.0f;

    // prefetch iter 0
    {
        {   // A: 64 rows x 64B = 256 chunks (1/thread)
            const int row = tid >> 2, cc = tid & 3;
            cpasync16(smu + (HA0 + row * 40) * 2 + cc * 16,
                      att + (size_t)row * Cch + cc * 8);
        }
        #pragma unroll
        for (int r = 0; r < 4; r++) {  // Wt: 256 rows x 64B = 1024 chunks
            const int idx = tid + r * 256;
            const int row = idx >> 2, cc = idx & 3;
            cpasync16(smu + (HW0 + row * 40) * 2 + cc * 16,
                      g_owT + (size_t)row * Cch + cc * 8);
        }
        CP_COMMIT();
    }

    for (int it = 0; it < 8; it++) {
        const int abuf = (it & 1) ? HA1 : HA0;
        const int wbuf = (it & 1) ? HW1 : HW0;
        if (it < 7) {
            const int k1 = (it + 1) * 32;
            const int a2 = (it & 1) ? HA0 : HA1;
            const int w2 = (it & 1) ? HW0 : HW1;
            {
                const int row = tid >> 2, cc = tid & 3;
                cpasync16(smu + (a2 + row * 40) * 2 + cc * 16,
                          att + (size_t)row * Cch + k1 + cc * 8);
            }
            #pragma unroll
            for (int r = 0; r < 4; r++) {
                const int idx = tid + r * 256;
                const int row = idx >> 2, cc = idx & 3;
                cpasync16(smu + (w2 + row * 40) * 2 + cc * 16,
                          g_owT + (size_t)row * Cch + k1 + cc * 8);
            }
            CP_COMMIT();
            CP_WAIT(1);
        } else {
            CP_WAIT(0);
        }
        __syncthreads();

        unsigned a[2][2][4];
        #pragma unroll
        for (int mt = 0; mt < 2; mt++) {
            const int row = m0 + mt * 16 + g;
            #pragma unroll
            for (int ks = 0; ks < 2; ks++) {
                const int kb = ks * 16 + 2 * tg;
                a[mt][ks][0] = *(const unsigned*)&smh[abuf + row * 40 + kb];
                a[mt][ks][1] = *(const unsigned*)&smh[abuf + (row + 8) * 40 + kb];
                a[mt][ks][2] = *(const unsigned*)&smh[abuf + row * 40 + kb + 8];
                a[mt][ks][3] = *(const unsigned*)&smh[abuf + (row + 8) * 40 + kb + 8];
            }
        }
        #pragma unroll
        for (int nt = 0; nt < 8; nt++) {
            const int cA = cg * 64 + nt * 8 + g;
            #pragma unroll
            for (int ks = 0; ks < 2; ks++) {
                const int kb = ks * 16 + 2 * tg;
                const unsigned b0 = *(const unsigned*)&smh[wbuf + cA * 40 + kb];
                const unsigned b1 = *(const unsigned*)&smh[wbuf + cA * 40 + kb + 8];
                mma16(acc[0][nt], a[0][ks], b0, b1);
                mma16(acc[1][nt], a[1][ks], b0, b1);
            }
        }
        __syncthreads();
    }

    #pragma unroll
    for (int mt = 0; mt < 2; mt++) {
        const int row = m0 + mt * 16 + g;
        #pragma unroll
        for (int nt = 0; nt < 8; nt++) {
            const int col = cg * 64 + nt * 8 + 2 * tg;
            *(float2*)&sm[row * 258 + col]       = make_float2(acc[mt][nt][0], acc[mt][nt][1]);
            *(float2*)&sm[(row + 8) * 258 + col] = make_float2(acc[mt][nt][2], acc[mt][nt][3]);
        }
    }
    __syncthreads();

    // transposed coalesced store: out[b][c][n0 + token]
    const int grp = tid >> 5;
    float* __restrict__ obp = out + (size_t)b * Cch * Nn + n0 + lane;
    #pragma unroll 4
    for (int it = 0; it < 32; it++) {
        const int c = it * 8 + grp;
        const float bias = ob[c];
        obp[(size_t)c * Nn]      = sm[lane * 258 + c] + bias;
        obp[(size_t)c * Nn + 32] = sm[(lane + 32) * 258 + c] + bias;
    }
}

// ---------------------------------------------------------------------------
extern "C" void kernel_launch(void* const* d_in, const int* in_sizes, int n_in,
                              void* d_out, int out_size)
{
    const float* fused_visual = (const float*)d_in[0];
    const float* text_emb     = (const float*)d_in[1];
    const float* q_w = (const float*)d_in[2];
    const float* q_b = (const float*)d_in[3];
    const float* k_w = (const float*)d_in[4];
    const float* k_b = (const float*)d_in[5];
    const float* v_w = (const float*)d_in[6];
    const float* v_b = (const float*)d_in[7];
    const float* o_w = (const float*)d_in[8];
    const float* o_b = (const float*)d_in[9];
    const float* m1_w = (const float*)d_in[10];
    const float* m1_b = (const float*)d_in[11];
    const float* m2_w = (const float*)d_in[12];
    const float* m2_b = (const float*)d_in[13];
    float* out = (float*)d_out;

    static int smem_ok = -1;
    if (smem_ok < 0) {
        cudaFuncSetAttribute(attn_kernel,  cudaFuncAttributeMaxDynamicSharedMemorySize, AT_BYTES);
        cudaFuncSetAttribute(qproj_kernel, cudaFuncAttributeMaxDynamicSharedMemorySize, QJ_BYTES);
        cudaFuncSetAttribute(oproj_kernel, cudaFuncAttributeMaxDynamicSharedMemorySize, OJ_BYTES);
        smem_ok = 1;
    }

    text_kernel<<<(Bv * Ss) / 8, 256>>>(text_emb, k_w, k_b, v_w, v_b, m1_w, m1_b, m2_w, m2_b);
    owt_kernel<<<64, 256>>>(o_w);
    qproj_kernel<<<Bv * (Nn / 64), 256, QJ_BYTES>>>(fused_visual, q_w, q_b);
    attn_kernel<<<dim3(Nn / 128, NH, Bv), 256, AT_BYTES>>>();
    oproj_kernel<<<Bv * (Nn / 64), 256, OJ_BYTES>>>(o_b, out);
}

// round 16
// speedup vs baseline: 1.2939x; 1.0225x over previous
#include <cuda_runtime.h>
#include <cuda_fp16.h>
#include <math.h>

// ---------------- problem constants ----------------
#define Bv   2
#define Cch  256
#define Nn   32768           // D*H*W
#define Ss   256
#define TDd  512
#define NH   8
#define HD   32
#define QSCALE 0.2550396392825023f    // 32^-0.5 * log2(e)

// ---------------- scratch ----------------
__device__ __half g_krotH[Bv * NH * Ss * HD];          // [b,h,s,hd]
__device__ __half g_vT   [Bv * NH * HD * Ss];          // [b,h,hd,s]  (transposed)
__device__ __half g_qrotH[(size_t)Bv * NH * Nn * HD];  // [b,h,n,hd]  pre-scaled
__device__ __half g_attH [(size_t)Bv * Nn * Cch];      // [b,n,c]
__device__ __half g_owT  [Cch * Cch];                  // o_w transposed [c][k] fp16
__device__ __half g_qwT  [Cch * Cch];                  // q_w transposed [c][k] fp16

// ---------------- helpers ----------------
__device__ __forceinline__ void mma16(float c[4], const unsigned a[4],
                                      unsigned b0, unsigned b1) {
    asm volatile(
        "mma.sync.aligned.m16n8k16.row.col.f32.f16.f16.f32 "
        "{%0,%1,%2,%3},{%4,%5,%6,%7},{%8,%9},{%0,%1,%2,%3};"
        : "+f"(c[0]), "+f"(c[1]), "+f"(c[2]), "+f"(c[3])
        : "r"(a[0]), "r"(a[1]), "r"(a[2]), "r"(a[3]), "r"(b0), "r"(b1));
}

__device__ __forceinline__ void cpasync16(unsigned dst, const void* src) {
    asm volatile("cp.async.ca.shared.global [%0], [%1], 16;" :: "r"(dst), "l"(src));
}
#define CP_COMMIT()  asm volatile("cp.async.commit_group;")
#define CP_WAIT(n)   asm volatile("cp.async.wait_group %0;" :: "n"(n))

// ---------------------------------------------------------------------------
// Kernel 0: transpose W [k][c] fp32 -> {g_owT|g_qwT} [c][k] fp16.
// Destination selected ON DEVICE (passing __device__ symbols from host is UB).
// ---------------------------------------------------------------------------
__global__ void wt_kernel(const float* __restrict__ src, int dst_sel)
{
    __half* __restrict__ dst = dst_sel ? g_qwT : g_owT;
    __shared__ float t[32][33];
    const int tx = threadIdx.x & 31;
    const int ty = threadIdx.x >> 5;           // 0..7
    const int c0 = (blockIdx.x & 7) * 32;
    const int k0 = (blockIdx.x >> 3) * 32;
    #pragma unroll
    for (int r = ty; r < 32; r += 8)
        t[r][tx] = src[(size_t)(k0 + r) * Cch + c0 + tx];
    __syncthreads();
    #pragma unroll
    for (int r = ty; r < 32; r += 8)
        dst[(size_t)(c0 + r) * Cch + k0 + tx] = __float2half(t[tx][r]);
}

// ---------------------------------------------------------------------------
// Kernel 1: text side (K/V proj, MLP phase, rope on K). 64 CTAs, tiny. FFMA.
// ---------------------------------------------------------------------------
__global__ void text_kernel(const float* __restrict__ text,
                            const float* __restrict__ k_w, const float* __restrict__ k_b,
                            const float* __restrict__ v_w, const float* __restrict__ v_b,
                            const float* __restrict__ m1_w, const float* __restrict__ m1_b,
                            const float* __restrict__ m2_w, const float* __restrict__ m2_b)
{
    __shared__ float t_s[8][TDd];
    __shared__ float h_s[8][Cch];
    __shared__ float k_s[8][Cch];

    const int tid  = threadIdx.x;
    const int row0 = blockIdx.x * 8;

    #pragma unroll
    for (int r = 0; r < 8; r++) {
        t_s[r][tid]       = text[(size_t)(row0 + r) * TDd + tid];
        t_s[r][tid + 256] = text[(size_t)(row0 + r) * TDd + tid + 256];
    }
    __syncthreads();

    float ka[8], va[8], ha[8];
    #pragma unroll
    for (int r = 0; r < 8; r++) { ka[r] = k_b[tid]; va[r] = v_b[tid]; ha[r] = m1_b[tid]; }

    for (int i = 0; i < TDd; i++) {
        const float wk = k_w[i * Cch + tid];
        const float wv = v_w[i * Cch + tid];
        const float wm = m1_w[i * Cch + tid];
        #pragma unroll
        for (int r = 0; r < 8; r++) {
            const float t = t_s[r][i];
            ka[r] += t * wk;  va[r] += t * wv;  ha[r] += t * wm;
        }
    }

    #pragma unroll
    for (int r = 0; r < 8; r++) {
        const float x = ha[r];
        h_s[r][tid] = 0.5f * x * (1.0f + erff(x * 0.7071067811865475f));
        k_s[r][tid] = ka[r];
    }
    __syncthreads();

    float pa[8];
    #pragma unroll
    for (int r = 0; r < 8; r++) pa[r] = m2_b[tid];
    for (int i = 0; i < Cch; i++) {
        const float wm2 = m2_w[i * Cch + tid];
        #pragma unroll
        for (int r = 0; r < 8; r++) pa[r] += h_s[r][i] * wm2;
    }

    const int j    = tid & 31;
    const int head = tid >> 5;
    const int part = (j < 16) ? tid + 16 : tid - 16;
    const float sgn = (j < 16) ? -1.0f : 1.0f;

    #pragma unroll
    for (int r = 0; r < 8; r++) {
        const int row = row0 + r;
        const int b = row >> 8;
        const int s = row & 255;
        float sf, cf;
        sincosf(pa[r], &sf, &cf);
        const float krot = k_s[r][tid] * cf + sgn * k_s[r][part] * sf;
        const int bh = b * NH + head;
        g_krotH[(bh * Ss + s) * HD + j]  = __float2half(krot);
        g_vT  [(bh * HD + j) * Ss + s]   = __float2half(va[r]);
    }
}

// ---------------------------------------------------------------------------
// Kernel 2: Q projection, FP16 m16n8k16 + rope epilogue (fp32) -> fp16 out.
// CTA = 64 tokens x 256 cols; A = fv tile transposed on the fly to fp16
// [tok][k] stride 40; W = g_qwT rows via cp.async, double-buffered.
// ---------------------------------------------------------------------------
#define QH_A0  0
#define QH_A1  2560           // 64*40
#define QH_W0  5120
#define QH_W1  15360          // +256*40
#define QTBf   16512          // float offset of rope tables
#define QJ_FLOATS (QTBf + 2048)
#define QJ_BYTES (QJ_FLOATS * 4)

__global__ void __launch_bounds__(256, 2) qproj_kernel(const float* __restrict__ fv,
                                                       const float* __restrict__ qb)
{
    extern __shared__ float sm[];
    __half* smh = (__half*)sm;
    const unsigned smu = (unsigned)__cvta_generic_to_shared(sm);
    float* TB = sm + QTBf;

    const int tid  = threadIdx.x;
    const int w    = tid >> 5;
    const int lane = tid & 31;
    const int g    = lane >> 2;
    const int tg   = lane & 3;
    const int b    = blockIdx.x >> 9;
    const int n0   = (blockIdx.x & 511) << 6;
    const int mg   = w >> 2;
    const int cg   = w & 3;
    const int m0   = mg * 32;

    // ---- build rope tables (4 sincos per thread) ----
    #pragma unroll
    for (int e = 0; e < 4; e++) {
        const int idx = tid + e * 256;
        const int pos = idx >> 5;
        const int jj  = idx & 31;
        float ex;
        if (jj < 10)      { const int z = jj;      ex = ((z < 5) ? z : z - 5) / 5.0f; }
        else if (jj < 20) { const int y = jj - 10; ex = ((y < 5) ? y : y - 5) / 5.0f; }
        else              { const int x = jj - 20; ex = ((x < 6) ? x : x - 6) / 6.0f; }
        const float invf = expf(-ex * 9.210340371976184f);
        float sf, cf;
        __sincosf((float)pos * invf, &sf, &cf);
        TB[idx]        = cf;
        TB[1024 + idx] = sf;
    }

    const float* __restrict__ fvb = fv + (size_t)b * Cch * Nn;

    float acc[2][8][4];
    #pragma unroll
    for (int mt = 0; mt < 2; mt++)
        #pragma unroll
        for (int nt = 0; nt < 8; nt++)
            #pragma unroll
            for (int i = 0; i < 4; i++) acc[mt][nt][i] = 0.0f;

    // ---- prefetch iter 0: A synchronously, W via cp.async ----
    {
        #pragma unroll
        for (int r = 0; r < 8; r++) {
            const int idx = tid + r * 256;
            const int kk = idx >> 6, nn = idx & 63;
            smh[QH_A0 + nn * 40 + kk] = __float2half(fvb[(size_t)kk * Nn + n0 + nn]);
        }
        #pragma unroll
        for (int r = 0; r < 4; r++) {
            const int idx = tid + r * 256;
            const int row = idx >> 2, cc = idx & 3;
            cpasync16(smu + (QH_W0 + row * 40) * 2 + cc * 16,
                      g_qwT + (size_t)row * Cch + cc * 8);
        }
        CP_COMMIT();
    }

    for (int it = 0; it < 8; it++) {
        const int abuf = (it & 1) ? QH_A1 : QH_A0;
        const int wbuf = (it & 1) ? QH_W1 : QH_W0;
        const int a2   = (it & 1) ? QH_A0 : QH_A1;
        float aval[8];
        if (it < 7) {
            const int k1 = (it + 1) * 32;
            #pragma unroll
            for (int r = 0; r < 8; r++) {
                const int idx = tid + r * 256;
                const int kk = idx >> 6, nn = idx & 63;
                aval[r] = fvb[(size_t)(k1 + kk) * Nn + n0 + nn];
            }
            const int w2 = (it & 1) ? QH_W0 : QH_W1;
            #pragma unroll
            for (int r = 0; r < 4; r++) {
                const int idx = tid + r * 256;
                const int row = idx >> 2, cc = idx & 3;
                cpasync16(smu + (w2 + row * 40) * 2 + cc * 16,
                          g_qwT + (size_t)row * Cch + k1 + cc * 8);
            }
            CP_COMMIT();
            CP_WAIT(1);
        } else {
            CP_WAIT(0);
        }
        __syncthreads();

        unsigned a[2][2][4];
        #pragma unroll
        for (int mt = 0; mt < 2; mt++) {
            const int row = m0 + mt * 16 + g;
            #pragma unroll
            for (int ks = 0; ks < 2; ks++) {
                const int kb = ks * 16 + 2 * tg;
                a[mt][ks][0] = *(const unsigned*)&smh[abuf + row * 40 + kb];
                a[mt][ks][1] = *(const unsigned*)&smh[abuf + (row + 8) * 40 + kb];
                a[mt][ks][2] = *(const unsigned*)&smh[abuf + row * 40 + kb + 8];
                a[mt][ks][3] = *(const unsigned*)&smh[abuf + (row + 8) * 40 + kb + 8];
            }
        }
        #pragma unroll
        for (int nt = 0; nt < 8; nt++) {
            const int cA = cg * 64 + nt * 8 + g;
            #pragma unroll
            for (int ks = 0; ks < 2; ks++) {
                const int kb = ks * 16 + 2 * tg;
                const unsigned b0 = *(const unsigned*)&smh[wbuf + cA * 40 + kb];
                const unsigned b1 = *(const unsigned*)&smh[wbuf + cA * 40 + kb + 8];
                mma16(acc[0][nt], a[0][ks], b0, b1);
                mma16(acc[1][nt], a[1][ks], b0, b1);
            }
        }

        if (it < 7) {
            #pragma unroll
            for (int r = 0; r < 8; r++) {
                const int idx = tid + r * 256;
                const int kk = idx >> 6, nn = idx & 63;
                smh[a2 + nn * 40 + kk] = __float2half(aval[r]);
            }
        }
        __syncthreads();
    }

    // write accums into OUT fp32 [64][258] (overlays staging)
    #pragma unroll
    for (int mt = 0; mt < 2; mt++) {
        const int row = m0 + mt * 16 + g;
        #pragma unroll
        for (int nt = 0; nt < 8; nt++) {
            const int col = cg * 64 + nt * 8 + 2 * tg;
            *(float2*)&sm[row * 258 + col]       = make_float2(acc[mt][nt][0], acc[mt][nt][1]);
            *(float2*)&sm[(row + 8) * 258 + col] = make_float2(acc[mt][nt][2], acc[mt][nt][3]);
        }
    }
    __syncthreads();

    // epilogue: bias + 3D rope + QSCALE, write fp16
    const int c    = tid;
    const int j    = c & 31;
    const int head = c >> 5;
    const int sel  = (j < 10) ? 0 : (j < 20) ? 1 : 2;
    const int part  = (j < 16) ? c + 16 : c - 16;
    const float sgn = (j < 16) ? -1.0f : 1.0f;
    const float qbc = qb[c], qbp = qb[part];

    __half* __restrict__ qo = g_qrotH + (((size_t)(b * NH + head)) * Nn) * HD + j;
    for (int nn = 0; nn < 64; nn++) {
        const int n  = n0 + nn;
        const int dz = n >> 10;
        const int hy = (n >> 5) & 31;
        const int wx = n & 31;
        const int posv = (sel == 0) ? dz : (sel == 1) ? hy : wx;
        const float cf = TB[posv * 32 + j];
        const float sf = TB[1024 + posv * 32 + j];
        const float qv = sm[nn * 258 + c]    + qbc;
        const float pv = sm[nn * 258 + part] + qbp;
        qo[(size_t)n * HD] = __float2half((qv * cf + sgn * pv * sf) * QSCALE);
    }
}

// ---------------------------------------------------------------------------
// Kernel 3: flash attention, FP16 m16n8k16. CTA = 128 queries (8 warps).
// ---------------------------------------------------------------------------
#define AQS  0
#define AKF  9216
#define AVT  (AKF + 256*40)          // 19456
#define AT_HALVES (AVT + 32*264)     // 27904
#define AT_BYTES (AT_HALVES * 2)     // 55808

__global__ void __launch_bounds__(256, 3) attn_kernel()
{
    extern __shared__ __half smh[];
    const unsigned smu = (unsigned)__cvta_generic_to_shared(smh);

    const int tid  = threadIdx.x;
    const int w    = tid >> 5;
    const int lane = tid & 31;
    const int g    = lane >> 2;
    const int tg   = lane & 3;
    const int n0   = blockIdx.x * 128;
    const int h    = blockIdx.y;
    const int b    = blockIdx.z;
    const size_t bh = (size_t)(b * NH + h);
    const int qr   = w * 16 + g;

    {
        #pragma unroll
        for (int r = 0; r < 2; r++) {
            const int idx = tid + r * 256;
            const int row = idx >> 2, cc = idx & 3;
            cpasync16(smu + (AQS + row * 40) * 2 + cc * 16,
                      g_qrotH + (bh * Nn + n0 + row) * HD + cc * 8);
        }
        #pragma unroll
        for (int r = 0; r < 4; r++) {
            const int idx = tid + r * 256;
            const int row = idx >> 2, cc = idx & 3;
            cpasync16(smu + (AKF + row * 40) * 2 + cc * 16,
                      g_krotH + (bh * Ss + row) * HD + cc * 8);
        }
        #pragma unroll
        for (int r = 0; r < 4; r++) {
            const int idx = tid + r * 256;
            const int row = idx >> 5, cc = idx & 31;
            cpasync16(smu + (AVT + row * 264) * 2 + cc * 16,
                      g_vT + (bh * HD + row) * Ss + cc * 8);
        }
        CP_COMMIT();
        CP_WAIT(0);
    }
    __syncthreads();

    unsigned aq[2][4];
    #pragma unroll
    for (int ks = 0; ks < 2; ks++) {
        const int kb = ks * 16 + 2 * tg;
        aq[ks][0] = *(const unsigned*)&smh[AQS + qr * 40 + kb];
        aq[ks][1] = *(const unsigned*)&smh[AQS + (qr + 8) * 40 + kb];
        aq[ks][2] = *(const unsigned*)&smh[AQS + qr * 40 + kb + 8];
        aq[ks][3] = *(const unsigned*)&smh[AQS + (qr + 8) * 40 + kb + 8];
    }
    __syncthreads();

    float m0, m1, l0, l1;
    float o[4][4];
    #pragma unroll
    for (int nt = 0; nt < 4; nt++)
        #pragma unroll
        for (int i = 0; i < 4; i++) o[nt][i] = 0.0f;

    #pragma unroll
    for (int ch = 0; ch < 4; ch++) {
        float c[8][4];
        #pragma unroll
        for (int nt = 0; nt < 8; nt++)
            #pragma unroll
            for (int i = 0; i < 4; i++) c[nt][i] = 0.0f;

        #pragma unroll
        for (int nt = 0; nt < 8; nt++) {
            const int key = ch * 64 + nt * 8 + g;
            #pragma unroll
            for (int ks = 0; ks < 2; ks++) {
                const int kb = ks * 16 + 2 * tg;
                const unsigned b0 = *(const unsigned*)&smh[AKF + key * 40 + kb];
                const unsigned b1 = *(const unsigned*)&smh[AKF + key * 40 + kb + 8];
                mma16(c[nt], aq[ks], b0, b1);
            }
        }

        float cm0 = -1e30f, cm1 = -1e30f;
        #pragma unroll
        for (int nt = 0; nt < 8; nt++) {
            cm0 = fmaxf(cm0, fmaxf(c[nt][0], c[nt][1]));
            cm1 = fmaxf(cm1, fmaxf(c[nt][2], c[nt][3]));
        }
        cm0 = fmaxf(cm0, __shfl_xor_sync(0xffffffffu, cm0, 1));
        cm0 = fmaxf(cm0, __shfl_xor_sync(0xffffffffu, cm0, 2));
        cm1 = fmaxf(cm1, __shfl_xor_sync(0xffffffffu, cm1, 1));
        cm1 = fmaxf(cm1, __shfl_xor_sync(0xffffffffu, cm1, 2));

        float sc0 = 1.0f, sc1 = 1.0f;
        if (ch == 0) {
            m0 = cm0; m1 = cm1;
        } else {
            const float mn0 = fmaxf(m0, cm0);
            const float mn1 = fmaxf(m1, cm1);
            sc0 = exp2f(m0 - mn0);
            sc1 = exp2f(m1 - mn1);
            m0 = mn0; m1 = mn1;
        }

        float s0 = 0.0f, s1 = 0.0f;
        #pragma unroll
        for (int nt = 0; nt < 8; nt++) {
            const float p0 = exp2f(c[nt][0] - m0);
            const float p1 = exp2f(c[nt][1] - m0);
            const float p2 = exp2f(c[nt][2] - m1);
            const float p3 = exp2f(c[nt][3] - m1);
            s0 += p0 + p1;  s1 += p2 + p3;
            *(__half2*)&smh[AQS + qr * 72 + nt * 8 + 2 * tg]       = __floats2half2_rn(p0, p1);
            *(__half2*)&smh[AQS + (qr + 8) * 72 + nt * 8 + 2 * tg] = __floats2half2_rn(p2, p3);
        }
        s0 += __shfl_xor_sync(0xffffffffu, s0, 1);
        s0 += __shfl_xor_sync(0xffffffffu, s0, 2);
        s1 += __shfl_xor_sync(0xffffffffu, s1, 1);
        s1 += __shfl_xor_sync(0xffffffffu, s1, 2);
        if (ch == 0) {
            l0 = s0;  l1 = s1;
        } else {
            l0 = l0 * sc0 + s0;
            l1 = l1 * sc1 + s1;
            #pragma unroll
            for (int nt = 0; nt < 4; nt++) {
                o[nt][0] *= sc0;  o[nt][1] *= sc0;
                o[nt][2] *= sc1;  o[nt][3] *= sc1;
            }
        }
        __syncwarp();

        #pragma unroll
        for (int ss = 0; ss < 4; ss++) {
            const int sb = ss * 16 + 2 * tg;
            unsigned a[4];
            a[0] = *(const unsigned*)&smh[AQS + qr * 72 + sb];
            a[1] = *(const unsigned*)&smh[AQS + (qr + 8) * 72 + sb];
            a[2] = *(const unsigned*)&smh[AQS + qr * 72 + sb + 8];
            a[3] = *(const unsigned*)&smh[AQS + (qr + 8) * 72 + sb + 8];
            const int s0i = ch * 64 + ss * 16 + 2 * tg;
            #pragma unroll
            for (int nt = 0; nt < 4; nt++) {
                const int hd = nt * 8 + g;
                const unsigned b0 = *(const unsigned*)&smh[AVT + hd * 264 + s0i];
                const unsigned b1 = *(const unsigned*)&smh[AVT + hd * 264 + s0i + 8];
                mma16(o[nt], a, b0, b1);
            }
        }
        __syncwarp();
    }

    const float r0 = 1.0f / l0;
    const float r1 = 1.0f / l1;
    #pragma unroll
    for (int nt = 0; nt < 4; nt++) {
        const int hd = nt * 8 + 2 * tg;
        __half* p0 = g_attH + ((size_t)(b * Nn + n0 + qr)) * Cch + h * HD + hd;
        __half* p1 = g_attH + ((size_t)(b * Nn + n0 + qr + 8)) * Cch + h * HD + hd;
        *(__half2*)p0 = __floats2half2_rn(o[nt][0] * r0, o[nt][1] * r0);
        *(__half2*)p1 = __floats2half2_rn(o[nt][2] * r1, o[nt][3] * r1);
    }
}

// ---------------------------------------------------------------------------
// Kernel 4: O projection + transpose, FP16 m16n8k16, cp.async double-buffered.
// ---------------------------------------------------------------------------
#define HA0  0
#define HA1  2560
#define HW0  5120
#define HW1  15360
#define OJ_BYTES (16512 * 4)

__global__ void __launch_bounds__(256, 2) oproj_kernel(const float* __restrict__ ob,
                                                       float* __restrict__ out)
{
    extern __shared__ float sm[];
    __half* smh = (__half*)sm;
    const unsigned smu = (unsigned)__cvta_generic_to_shared(sm);

    const int tid  = threadIdx.x;
    const int w    = tid >> 5;
    const int lane = tid & 31;
    const int g    = lane >> 2;
    const int tg   = lane & 3;
    const int b    = blockIdx.x >> 9;
    const int n0   = (blockIdx.x & 511) << 6;
    const int mg   = w >> 2;
    const int cg   = w & 3;
    const int m0   = mg * 32;

    const __half* __restrict__ att = g_attH + ((size_t)(b * Nn + n0)) * Cch;

    float acc[2][8][4];
    #pragma unroll
    for (int mt = 0; mt < 2; mt++)
        #pragma unroll
        for (int nt = 0; nt < 8; nt++)
            #pragma unroll
            for (int i = 0; i < 4; i++) acc[mt][nt][i] = 0.0f;

    {
        {
            const int row = tid >> 2, cc = tid & 3;
            cpasync16(smu + (HA0 + row * 40) * 2 + cc * 16,
                      att + (size_t)row * Cch + cc * 8);
        }
        #pragma unroll
        for (int r = 0; r < 4; r++) {
            const int idx = tid + r * 256;
            const int row = idx >> 2, cc = idx & 3;
            cpasync16(smu + (HW0 + row * 40) * 2 + cc * 16,
                      g_owT + (size_t)row * Cch + cc * 8);
        }
        CP_COMMIT();
    }

    for (int it = 0; it < 8; it++) {
        const int abuf = (it & 1) ? HA1 : HA0;
        const int wbuf = (it & 1) ? HW1 : HW0;
        if (it < 7) {
            const int k1 = (it + 1) * 32;
            const int a2 = (it & 1) ? HA0 : HA1;
            const int w2 = (it & 1) ? HW0 : HW1;
            {
                const int row = tid >> 2, cc = tid & 3;
                cpasync16(smu + (a2 + row * 40) * 2 + cc * 16,
                          att + (size_t)row * Cch + k1 + cc * 8);
            }
            #pragma unroll
            for (int r = 0; r < 4; r++) {
                const int idx = tid + r * 256;
                const int row = idx >> 2, cc = idx & 3;
                cpasync16(smu + (w2 + row * 40) * 2 + cc * 16,
                          g_owT + (size_t)row * Cch + k1 + cc * 8);
            }
            CP_COMMIT();
            CP_WAIT(1);
        } else {
            CP_WAIT(0);
        }
        __syncthreads();

        unsigned a[2][2][4];
        #pragma unroll
        for (int mt = 0; mt < 2; mt++) {
            const int row = m0 + mt * 16 + g;
            #pragma unroll
            for (int ks = 0; ks < 2; ks++) {
                const int kb = ks * 16 + 2 * tg;
                a[mt][ks][0] = *(const unsigned*)&smh[abuf + row * 40 + kb];
                a[mt][ks][1] = *(const unsigned*)&smh[abuf + (row + 8) * 40 + kb];
                a[mt][ks][2] = *(const unsigned*)&smh[abuf + row * 40 + kb + 8];
                a[mt][ks][3] = *(const unsigned*)&smh[abuf + (row + 8) * 40 + kb + 8];
            }
        }
        #pragma unroll
        for (int nt = 0; nt < 8; nt++) {
            const int cA = cg * 64 + nt * 8 + g;
            #pragma unroll
            for (int ks = 0; ks < 2; ks++) {
                const int kb = ks * 16 + 2 * tg;
                const unsigned b0 = *(const unsigned*)&smh[wbuf + cA * 40 + kb];
                const unsigned b1 = *(const unsigned*)&smh[wbuf + cA * 40 + kb + 8];
                mma16(acc[0][nt], a[0][ks], b0, b1);
                mma16(acc[1][nt], a[1][ks], b0, b1);
            }
        }
        __syncthreads();
    }

    #pragma unroll
    for (int mt = 0; mt < 2; mt++) {
        const int row = m0 + mt * 16 + g;
        #pragma unroll
        for (int nt = 0; nt < 8; nt++) {
            const int col = cg * 64 + nt * 8 + 2 * tg;
            *(float2*)&sm[row * 258 + col]       = make_float2(acc[mt][nt][0], acc[mt][nt][1]);
            *(float2*)&sm[(row + 8) * 258 + col] = make_float2(acc[mt][nt][2], acc[mt][nt][3]);
        }
    }
    __syncthreads();

    const int grp = tid >> 5;
    float* __restrict__ obp = out + (size_t)b * Cch * Nn + n0 + lane;
    #pragma unroll 4
    for (int it = 0; it < 32; it++) {
        const int c = it * 8 + grp;
        const float bias = ob[c];
        obp[(size_t)c * Nn]      = sm[lane * 258 + c] + bias;
        obp[(size_t)c * Nn + 32] = sm[(lane + 32) * 258 + c] + bias;
    }
}

// ---------------------------------------------------------------------------
extern "C" void kernel_launch(void* const* d_in, const int* in_sizes, int n_in,
                              void* d_out, int out_size)
{
    const float* fused_visual = (const float*)d_in[0];
    const float* text_emb     = (const float*)d_in[1];
    const float* q_w = (const float*)d_in[2];
    const float* q_b = (const float*)d_in[3];
    const float* k_w = (const float*)d_in[4];
    const float* k_b = (const float*)d_in[5];
    const float* v_w = (const float*)d_in[6];
    const float* v_b = (const float*)d_in[7];
    const float* o_w = (const float*)d_in[8];
    const float* o_b = (const float*)d_in[9];
    const float* m1_w = (const float*)d_in[10];
    const float* m1_b = (const float*)d_in[11];
    const float* m2_w = (const float*)d_in[12];
    const float* m2_b = (const float*)d_in[13];
    float* out = (float*)d_out;

    static int smem_ok = -1;
    if (smem_ok < 0) {
        cudaFuncSetAttribute(attn_kernel,  cudaFuncAttributeMaxDynamicSharedMemorySize, AT_BYTES);
        cudaFuncSetAttribute(qproj_kernel, cudaFuncAttributeMaxDynamicSharedMemorySize, QJ_BYTES);
        cudaFuncSetAttribute(oproj_kernel, cudaFuncAttributeMaxDynamicSharedMemorySize, OJ_BYTES);
        smem_ok = 1;
    }

    text_kernel<<<(Bv * Ss) / 8, 256>>>(text_emb, k_w, k_b, v_w, v_b, m1_w, m1_b, m2_w, m2_b);
    wt_kernel<<<64, 256>>>(o_w, 0);
    wt_kernel<<<64, 256>>>(q_w, 1);
    qproj_kernel<<<Bv * (Nn / 64), 256, QJ_BYTES>>>(fused_visual, q_b);
    attn_kernel<<<dim3(Nn / 128, NH, Bv), 256, AT_BYTES>>>();
    oproj_kernel<<<Bv * (Nn / 64), 256, OJ_BYTES>>>(o_b, out);
}